// round 3
// baseline (speedup 1.0000x reference)
#include <cuda_runtime.h>
#include <math.h>

// Shapes (fixed): B=4, S=128, D=256, H=8, HD=32, HID=256, NS=129
#define NEGV -1000000000.0f

// ---------------- scratch (device globals) ----------------------------------
__device__ float g_t1[512 * 256];
__device__ float g_t2[512 * 256];
__device__ float g_dh[512 * 256];
__device__ float g_dt[512 * 256];
__device__ float g_vh[512 * 256];
__device__ float g_vt[512 * 256];
__device__ float g_Pa[512 * 256];
__device__ float g_Pb[512 * 256];
__device__ float g_q[516 * 256];
__device__ float g_k[516 * 256];
__device__ float g_v[516 * 256];
__device__ float g_D[4 * 128 * 128];
__device__ float g_V[4 * 128 * 128];
__device__ float g_dot[4 * 128 * 128];
__device__ float g_qs[4 * 8 * 129];
__device__ float g_ks[4 * 8 * 129];
__device__ float g_ctx[516 * 256];
__device__ float g_M[256 * 8];
__device__ float g_biasE[8];
__device__ float g_S1a[512], g_Qa[512], g_S1b[512], g_Qb[512];
__device__ float g_invDh[512], g_invDt[512];

// ---------------- reduction helpers ----------------------------------------
__device__ __forceinline__ float warpSum(float v) {
#pragma unroll
    for (int o = 16; o > 0; o >>= 1) v += __shfl_xor_sync(0xffffffffu, v, o);
    return v;
}
__device__ __forceinline__ float warpMax(float v) {
#pragma unroll
    for (int o = 16; o > 0; o >>= 1) v = fmaxf(v, __shfl_xor_sync(0xffffffffu, v, o));
    return v;
}

// ---------------- generic 64x64x256 fp32 GEMM tile --------------------------
__device__ __forceinline__ void gemm_tile(const float* __restrict__ A, int M,
                                          const float* __restrict__ W,
                                          const float* __restrict__ bias,
                                          float* __restrict__ C, int doRelu,
                                          int srcSkip) {
    __shared__ __align__(16) float Ast[16][64];  // [k][m]
    __shared__ __align__(16) float Ws[16][64];   // [k][n]
    const int tid = threadIdx.x;  // 256 threads
    const int rowBase = blockIdx.y * 64;
    const int colBase = blockIdx.x * 64;
    if (rowBase >= M) return;
    const int tx = tid & 15, ty = tid >> 4;
    float acc[4][4] = {};
    const int aRow = tid >> 2;
    const int aK4 = (tid & 3) * 4;
    const int wK = tid >> 4;
    const int wC4 = (tid & 15) * 4;
    int row = rowBase + aRow;
    int srow = srcSkip ? (row + (row >> 7) + 1) : row;
    for (int k0 = 0; k0 < 256; k0 += 16) {
        float4 av;
        if (row < M)
            av = *(const float4*)(A + (size_t)srow * 256 + k0 + aK4);
        else
            av = make_float4(0.f, 0.f, 0.f, 0.f);
        Ast[aK4 + 0][aRow] = av.x;
        Ast[aK4 + 1][aRow] = av.y;
        Ast[aK4 + 2][aRow] = av.z;
        Ast[aK4 + 3][aRow] = av.w;
        *(float4*)&Ws[wK][wC4] =
            *(const float4*)(W + (size_t)(k0 + wK) * 256 + colBase + wC4);
        __syncthreads();
#pragma unroll
        for (int kk = 0; kk < 16; kk++) {
            float4 a = *(const float4*)&Ast[kk][ty * 4];
            float4 b = *(const float4*)&Ws[kk][tx * 4];
            acc[0][0] += a.x * b.x; acc[0][1] += a.x * b.y; acc[0][2] += a.x * b.z; acc[0][3] += a.x * b.w;
            acc[1][0] += a.y * b.x; acc[1][1] += a.y * b.y; acc[1][2] += a.y * b.z; acc[1][3] += a.y * b.w;
            acc[2][0] += a.z * b.x; acc[2][1] += a.z * b.y; acc[2][2] += a.z * b.z; acc[2][3] += a.z * b.w;
            acc[3][0] += a.w * b.x; acc[3][1] += a.w * b.y; acc[3][2] += a.w * b.z; acc[3][3] += a.w * b.w;
        }
        __syncthreads();
    }
    float4 bv = bias ? *(const float4*)(bias + colBase + tx * 4)
                     : make_float4(0.f, 0.f, 0.f, 0.f);
#pragma unroll
    for (int r = 0; r < 4; r++) {
        int orow = rowBase + ty * 4 + r;
        if (orow < M) {
            float4 o;
            o.x = acc[r][0] + bv.x; o.y = acc[r][1] + bv.y;
            o.z = acc[r][2] + bv.z; o.w = acc[r][3] + bv.w;
            if (doRelu) {
                o.x = fmaxf(o.x, 0.f); o.y = fmaxf(o.y, 0.f);
                o.z = fmaxf(o.z, 0.f); o.w = fmaxf(o.w, 0.f);
            }
            *(float4*)(C + (size_t)orow * 256 + colBase + tx * 4) = o;
        }
    }
}

// ---------------- GEMM phase A: 9 independent GEMMs -------------------------
__global__ __launch_bounds__(256) void phaseA_kernel(
    const float* desc, const float* nv,
    const float* th_w1, const float* th_b1,
    const float* tt_w1, const float* tt_b1,
    const float* ah_w, const float* ah_b,
    const float* at_w, const float* at_b,
    const float* eu_w1, const float* eu_b1,
    const float* q_w, const float* q_b,
    const float* k_w, const float* k_b,
    const float* v_w, const float* v_b) {
    const float *A, *W, *bias;
    float* C;
    int M = 512, relu = 0, skip = 0;
    switch (blockIdx.z) {
        case 0: A = desc; W = th_w1; bias = th_b1; C = g_t1; relu = 1; break;
        case 1: A = desc; W = tt_w1; bias = tt_b1; C = g_t2; relu = 1; break;
        case 2: A = nv;   W = ah_w;  bias = ah_b;  C = g_vh; skip = 1; break;
        case 3: A = nv;   W = at_w;  bias = at_b;  C = g_vt; skip = 1; break;
        case 4: A = desc; W = eu_w1;             bias = eu_b1;  C = g_Pa; break;
        case 5: A = desc; W = eu_w1 + 256 * 256; bias = nullptr; C = g_Pb; break;
        case 6: A = nv;   W = q_w;   bias = q_b;   C = g_q; M = 516; break;
        case 7: A = nv;   W = k_w;   bias = k_b;   C = g_k; M = 516; break;
        default: A = nv;  W = v_w;   bias = v_b;   C = g_v; M = 516; break;
    }
    gemm_tile(A, M, W, bias, C, relu, skip);
}

// ---------------- GEMM phase B: dh, dt --------------------------------------
__global__ __launch_bounds__(256) void phaseB_kernel(
    const float* th_w2, const float* th_b2,
    const float* tt_w2, const float* tt_b2) {
    if (blockIdx.z == 0)
        gemm_tile(g_t1, 512, th_w2, th_b2, g_dh, 0, 0);
    else
        gemm_tile(g_t2, 512, tt_w2, tt_b2, g_dt, 0, 0);
}

// ---------------- qs/ks dots + M fold + row stats + row norms ---------------
__global__ __launch_bounds__(256) void qsksM_kernel(
    const float* __restrict__ ap_w,
    const float* __restrict__ eu_w2,
    const float* __restrict__ eu_b2) {
    int tid = threadIdx.x;  // 256
    int bx = blockIdx.x;
    int w = tid >> 5, lane = tid & 31;
    if (bx < 516) {
        int row = bx;  // b*129+i
        int b = row / 129, iN = row % 129;
        int h = w;
        float qv = g_q[(size_t)row * 256 + tid] * ap_w[lane];
        float kv = g_k[(size_t)row * 256 + tid] * ap_w[32 + lane];
        qv = warpSum(qv);
        kv = warpSum(kv);
        if (lane == 0) {
            g_qs[(size_t)(b * 8 + h) * 129 + iN] = qv;
            g_ks[(size_t)(b * 8 + h) * 129 + iN] = kv;
        }
    } else if (bx == 516) {
        int c = tid;
#pragma unroll
        for (int h = 0; h < 8; h++) {
            float s = 0.f;
#pragma unroll
            for (int t = 0; t < 32; t++)
                s += eu_w2[c * 256 + h * 32 + t] * ap_w[64 + t];
            g_M[c * 8 + h] = s;
        }
        if (tid < 8) {
            float s = 0.f;
#pragma unroll
            for (int t = 0; t < 32; t++) s += eu_b2[tid * 32 + t] * ap_w[64 + t];
            g_biasE[tid] = s;
        }
    } else if (bx < 645) {
        // Pa/Pb row sums + sumsq: rows 0..1023 (Pa rows 0..511, Pb rows 512..1023)
        int row = (bx - 517) * 8 + w;
        const float* src = (row < 512) ? (g_Pa + (size_t)row * 256)
                                       : (g_Pb + (size_t)(row - 512) * 256);
        float s1 = 0.f, q = 0.f;
#pragma unroll
        for (int t = 0; t < 8; t++) {
            float v = src[lane + t * 32];
            s1 += v;
            q += v * v;
        }
        s1 = warpSum(s1);
        q = warpSum(q);
        if (lane == 0) {
            if (row < 512) { g_S1a[row] = s1; g_Qa[row] = q; }
            else           { g_S1b[row - 512] = s1; g_Qb[row - 512] = q; }
        }
    } else {
        // dh/dt row inverse norms: rows 0..1023
        int row = (bx - 645) * 8 + w;
        const float* src = (row < 512) ? (g_dh + (size_t)row * 256)
                                       : (g_dt + (size_t)(row - 512) * 256);
        float ss = 0.f;
#pragma unroll
        for (int t = 0; t < 8; t++) {
            float v = src[lane + t * 32];
            ss += v * v;
        }
        ss = warpSum(ss);
        if (lane == 0) {
            float inv = rsqrtf(ss);
            if (row < 512) g_invDh[row] = inv;
            else           g_invDt[row - 512] = inv;
        }
    }
}

// ---------------- products: D=dh.dt^T, V=vh.vt^T, dot=Pa.Pb^T ---------------
__global__ __launch_bounds__(256) void products_kernel() {
    int z = blockIdx.z;
    int b = z / 3, p = z % 3;
    const float *X, *Y;
    float* C;
    if (p == 0)      { X = g_dh; Y = g_dt; C = g_D; }
    else if (p == 1) { X = g_vh; Y = g_vt; C = g_V; }
    else             { X = g_Pa; Y = g_Pb; C = g_dot; }
    __shared__ __align__(16) float Ast[16][64];  // [k][i]
    __shared__ __align__(16) float Bst[16][64];  // [k][j]
    const int tid = threadIdx.x;
    const int rowBase = blockIdx.y * 64;
    const int colBase = blockIdx.x * 64;
    const int tx = tid & 15, ty = tid >> 4;
    float acc[4][4] = {};
    const int aRow = tid >> 2;       // 0..63
    const int aK4 = (tid & 3) * 4;   // 0,4,8,12
    for (int k0 = 0; k0 < 256; k0 += 16) {
        float4 av = *(const float4*)(X + (size_t)(b * 128 + rowBase + aRow) * 256 + k0 + aK4);
        Ast[aK4 + 0][aRow] = av.x;
        Ast[aK4 + 1][aRow] = av.y;
        Ast[aK4 + 2][aRow] = av.z;
        Ast[aK4 + 3][aRow] = av.w;
        float4 bv = *(const float4*)(Y + (size_t)(b * 128 + colBase + aRow) * 256 + k0 + aK4);
        Bst[aK4 + 0][aRow] = bv.x;
        Bst[aK4 + 1][aRow] = bv.y;
        Bst[aK4 + 2][aRow] = bv.z;
        Bst[aK4 + 3][aRow] = bv.w;
        __syncthreads();
#pragma unroll
        for (int kk = 0; kk < 16; kk++) {
            float4 a = *(const float4*)&Ast[kk][ty * 4];
            float4 bb = *(const float4*)&Bst[kk][tx * 4];
            acc[0][0] += a.x * bb.x; acc[0][1] += a.x * bb.y; acc[0][2] += a.x * bb.z; acc[0][3] += a.x * bb.w;
            acc[1][0] += a.y * bb.x; acc[1][1] += a.y * bb.y; acc[1][2] += a.y * bb.z; acc[1][3] += a.y * bb.w;
            acc[2][0] += a.z * bb.x; acc[2][1] += a.z * bb.y; acc[2][2] += a.z * bb.z; acc[2][3] += a.z * bb.w;
            acc[3][0] += a.w * bb.x; acc[3][1] += a.w * bb.y; acc[3][2] += a.w * bb.z; acc[3][3] += a.w * bb.w;
        }
        __syncthreads();
    }
#pragma unroll
    for (int r = 0; r < 4; r++) {
        int orow = b * 128 + rowBase + ty * 4 + r;
        *(float4*)(C + (size_t)orow * 128 + colBase + tx * 4) =
            make_float4(acc[r][0], acc[r][1], acc[r][2], acc[r][3]);
    }
}

// ---------------- mega: adj row + scores + softmax + ctx per (b,i) ----------
__global__ __launch_bounds__(256) void mega_kernel(
    const float* __restrict__ eu_g, const float* __restrict__ eu_beta,
    const float* __restrict__ ap_b_p, const float* __restrict__ topo,
    const float* __restrict__ alphap, float* __restrict__ attn_out) {
    int i = blockIdx.x;  // 0..128
    int b = blockIdx.y;
    __shared__ float sg[256], sbt[256];
    __shared__ __align__(16) float sM[2048];
    __shared__ float sks[8 * 129];
    __shared__ float sqs[8], sbe[8];
    __shared__ __align__(16) float sPa[256];
    __shared__ float sAdj[128];
    __shared__ float sSc[8][132];
    __shared__ float red[8];
    int tid = threadIdx.x;  // 256
    int w = tid >> 5, lane = tid & 31;
    sg[tid] = eu_g[tid];
    sbt[tid] = eu_beta[tid];
    for (int t = tid; t < 2048; t += 256) sM[t] = g_M[t];
    for (int t = tid; t < 1032; t += 256) sks[t] = g_ks[(size_t)b * 1032 + t];
    if (tid < 8) {
        sqs[tid] = g_qs[(size_t)(b * 8 + tid) * 129 + i];
        sbe[tid] = g_biasE[tid];
    }
    if (i >= 1) sPa[tid] = g_Pa[(size_t)(b * 128 + i - 1) * 256 + tid];
    __syncthreads();

    // ---- adj row (i >= 1 only) ----
    if (i >= 1) {
        int r = b * 128 + i - 1;
        float graw = NEGV;
        if (tid < 128) {
            float d = g_D[(size_t)r * 128 + tid] * g_invDh[r] * g_invDt[b * 128 + tid];
            float a = 1.f / (1.f + expf(-(d + topo[0])));
            graw = (tid == i - 1) ? NEGV : a * g_V[(size_t)r * 128 + tid];
        }
        float m = warpMax(graw);
        if (lane == 0) red[w] = m;
        __syncthreads();
        float mx = fmaxf(fmaxf(red[0], red[1]), fmaxf(red[2], red[3]));
        float alpha = fminf(fmaxf(alphap[0], 1e-5f), 1.0f);
        float thr = mx * alpha;
        float e = (tid < 128 && graw >= thr) ? expf(graw - mx) : 0.f;
        float s = warpSum(e);
        __syncthreads();
        if (lane == 0) red[w] = s;
        __syncthreads();
        float Z = red[0] + red[1] + red[2] + red[3] +
                  red[4] + red[5] + red[6] + red[7];
        float invZ = (Z > 0.f) ? 1.f / Z : 0.f;
        if (tid < 128) sAdj[tid] = e * invZ;
        __syncthreads();
    }

    // ---- scores: 4 j per warp, 8 lanes per j, 32 channels per lane ----
    float apb = ap_b_p[0];
    int g = lane >> 3, sl = lane & 7;
    for (int t = 0; t < 5; t++) {
        int j = t * 32 + w * 4 + g;  // 0..159
        bool valid = (j < 129);
        float na = 0.f;
        if (valid) {
            if (i == 0) na = (j == 0) ? 0.f : 1.f;
            else        na = (j == 0) ? 0.f : sAdj[j - 1];
        }
        float acc[8] = {0.f, 0.f, 0.f, 0.f, 0.f, 0.f, 0.f, 0.f};
        if (valid && na != 0.f) {
            int ja = j - 1;
            int ia = (i >= 1) ? (i - 1) : ja;
            int ra = b * 128 + ia, rb = b * 128 + ja;
            float S1 = g_S1a[ra] + g_S1b[rb];
            float Qs = g_Qa[ra] + g_Qb[rb] + 2.f * g_dot[(size_t)ra * 128 + ja];
            float mu = S1 * (1.f / 256.f);
            float var = Qs * (1.f / 256.f) - mu * mu;
            float inv = rsqrtf(var + 1e-5f);
            const float4* pb4 = (const float4*)(g_Pb + (size_t)rb * 256);
            const float4* pa4 = (const float4*)(g_Pa + (size_t)rb * 256);
            int c0 = sl * 32;
#pragma unroll
            for (int u = 0; u < 8; u++) {
                int c = c0 + u * 4;
                float4 bv = pb4[c >> 2];
                float4 av = (i >= 1) ? *(const float4*)&sPa[c] : pa4[c >> 2];
                float4 gv = *(const float4*)&sg[c];
                float4 btv = *(const float4*)&sbt[c];
                float r0 = fmaxf((av.x + bv.x - mu) * inv * gv.x + btv.x, 0.f);
                float r1 = fmaxf((av.y + bv.y - mu) * inv * gv.y + btv.y, 0.f);
                float r2 = fmaxf((av.z + bv.z - mu) * inv * gv.z + btv.z, 0.f);
                float r3 = fmaxf((av.w + bv.w - mu) * inv * gv.w + btv.w, 0.f);
#pragma unroll
                for (int q = 0; q < 4; q++) {
                    float rr = (q == 0) ? r0 : (q == 1) ? r1 : (q == 2) ? r2 : r3;
                    const float4 m0 = *(const float4*)&sM[(c + q) * 8];
                    const float4 m1 = *(const float4*)&sM[(c + q) * 8 + 4];
                    acc[0] += rr * m0.x; acc[1] += rr * m0.y;
                    acc[2] += rr * m0.z; acc[3] += rr * m0.w;
                    acc[4] += rr * m1.x; acc[5] += rr * m1.y;
                    acc[6] += rr * m1.z; acc[7] += rr * m1.w;
                }
            }
        }
        // reduce over the 8 sublanes of each group (full-warp shfl, groups aligned)
#pragma unroll
        for (int off = 1; off < 8; off <<= 1) {
#pragma unroll
            for (int h = 0; h < 8; h++)
                acc[h] += __shfl_xor_sync(0xffffffffu, acc[h], off);
        }
        if (valid) {
            float eterm = acc[sl] + sbe[sl];
            float sc = sqs[sl] + sks[sl * 129 + j] + apb +
                       ((na == 0.f) ? NEGV : eterm * na);
            sSc[sl][j] = sc;
        }
    }
    __syncthreads();

    // ---- softmax per head (warp w == head) ----
    {
        int h = w;
        float x0 = sSc[h][lane], x1 = sSc[h][lane + 32];
        float x2 = sSc[h][lane + 64], x3 = sSc[h][lane + 96];
        float xt = (lane == 0) ? sSc[h][128] : NEGV;
        float m = fmaxf(fmaxf(x0, x1), fmaxf(fmaxf(x2, x3), xt));
        m = warpMax(m);
        float e0 = expf(x0 - m), e1 = expf(x1 - m);
        float e2 = expf(x2 - m), e3 = expf(x3 - m);
        float et = (lane == 0) ? expf(xt - m) : 0.f;
        float s = e0 + e1 + e2 + e3 + et;
        s = warpSum(s);
        float invZ = 1.f / s;
        sSc[h][lane] = e0 * invZ;
        sSc[h][lane + 32] = e1 * invZ;
        sSc[h][lane + 64] = e2 * invZ;
        sSc[h][lane + 96] = e3 * invZ;
        if (lane == 0) sSc[h][128] = et * invZ;
        if (attn_out) {
            float* ap = attn_out + ((size_t)(b * 8 + h) * 129 + i) * 129;
            ap[lane] = e0 * invZ;
            ap[lane + 32] = e1 * invZ;
            ap[lane + 64] = e2 * invZ;
            ap[lane + 96] = e3 * invZ;
            if (lane == 0) ap[128] = et * invZ;
        }
    }
    __syncthreads();

    // ---- ctx: warp h computes channels h*32+lane ----
    {
        int h = w;
        const float* vbase = g_v + (size_t)b * 129 * 256 + h * 32 + lane;
        float acc = 0.f;
#pragma unroll 4
        for (int j = 0; j < 128; j += 4) {
            acc += sSc[h][j + 0] * vbase[(size_t)(j + 0) * 256];
            acc += sSc[h][j + 1] * vbase[(size_t)(j + 1) * 256];
            acc += sSc[h][j + 2] * vbase[(size_t)(j + 2) * 256];
            acc += sSc[h][j + 3] * vbase[(size_t)(j + 3) * 256];
        }
        acc += sSc[h][128] * vbase[(size_t)128 * 256];
        g_ctx[(size_t)(b * 129 + i) * 256 + h * 32 + lane] = acc;
    }
}

// ---------------- final out GEMM --------------------------------------------
__global__ __launch_bounds__(256) void phaseC_kernel(const float* out_w,
                                                     const float* out_b,
                                                     float* out) {
    gemm_tile(g_ctx, 516, out_w, out_b, out, 0, 0);
}

// ---------------- launch -----------------------------------------------------
extern "C" void kernel_launch(void* const* d_in, const int* in_sizes, int n_in,
                              void* d_out, int out_size) {
    const float* desc   = (const float*)d_in[0];
    const float* nv     = (const float*)d_in[1];
    const float* th_w1  = (const float*)d_in[2];
    const float* th_b1  = (const float*)d_in[3];
    const float* th_w2  = (const float*)d_in[4];
    const float* th_b2  = (const float*)d_in[5];
    const float* tt_w1  = (const float*)d_in[6];
    const float* tt_b1  = (const float*)d_in[7];
    const float* tt_w2  = (const float*)d_in[8];
    const float* tt_b2  = (const float*)d_in[9];
    const float* ah_w   = (const float*)d_in[10];
    const float* ah_b   = (const float*)d_in[11];
    const float* at_w   = (const float*)d_in[12];
    const float* at_b   = (const float*)d_in[13];
    const float* q_w    = (const float*)d_in[14];
    const float* q_b    = (const float*)d_in[15];
    const float* k_w    = (const float*)d_in[16];
    const float* k_b    = (const float*)d_in[17];
    const float* v_w    = (const float*)d_in[18];
    const float* v_b    = (const float*)d_in[19];
    const float* eu_w1  = (const float*)d_in[20];
    const float* eu_b1  = (const float*)d_in[21];
    const float* eu_g   = (const float*)d_in[22];
    const float* eu_beta= (const float*)d_in[23];
    const float* eu_w2  = (const float*)d_in[24];
    const float* eu_b2  = (const float*)d_in[25];
    const float* ap_w   = (const float*)d_in[26];
    const float* ap_b   = (const float*)d_in[27];
    const float* out_w  = (const float*)d_in[28];
    const float* out_b  = (const float*)d_in[29];
    const float* topo   = (const float*)d_in[30];
    const float* alphap = (const float*)d_in[31];

    const int OUT_ELEMS = 4 * 129 * 256;          // 132096
    const int ATTN_ELEMS = 4 * 8 * 129 * 129;     // 532512
    float* out = (float*)d_out;
    float* attn_out = (out_size >= OUT_ELEMS + ATTN_ELEMS) ? (out + OUT_ELEMS)
                                                           : nullptr;

    phaseA_kernel<<<dim3(4, 9, 9), 256>>>(desc, nv, th_w1, th_b1, tt_w1, tt_b1,
                                          ah_w, ah_b, at_w, at_b, eu_w1, eu_b1,
                                          q_w, q_b, k_w, k_b, v_w, v_b);
    phaseB_kernel<<<dim3(4, 8, 2), 256>>>(th_w2, th_b2, tt_w2, tt_b2);
    qsksM_kernel<<<773, 256>>>(ap_w, eu_w2, eu_b2);
    products_kernel<<<dim3(2, 2, 12), 256>>>();
    mega_kernel<<<dim3(129, 4), 256>>>(eu_g, eu_beta, ap_b, topo, alphap,
                                       attn_out);
    phaseC_kernel<<<dim3(4, 9, 1), 256>>>(out_w, out_b, out);
}

// round 4
// speedup vs baseline: 1.4673x; 1.4673x over previous
#include <cuda_runtime.h>
#include <math.h>

// Shapes (fixed): B=4, S=128, D=256, H=8, HD=32, HID=256, NS=129
#define NEGV -1000000000.0f

// ---------------- scratch (device globals) ----------------------------------
__device__ float g_t1[512 * 256];
__device__ float g_t2[512 * 256];
__device__ float g_dh[512 * 256];
__device__ float g_dt[512 * 256];
__device__ float g_vh[512 * 256];
__device__ float g_vt[512 * 256];
__device__ float g_Pa[512 * 256];
__device__ float g_Pb[512 * 256];
__device__ float g_q[516 * 256];
__device__ float g_k[516 * 256];
__device__ float g_v[516 * 256];
__device__ float g_G[4 * 128 * 128];
__device__ float g_qs[4 * 8 * 129];
__device__ float g_ks[4 * 8 * 129];
__device__ float g_ctx[516 * 256];
__device__ float g_M[256 * 8];
__device__ float g_biasE[8];

// ---------------- reduction helpers ----------------------------------------
__device__ __forceinline__ float warpSum(float v) {
#pragma unroll
    for (int o = 16; o > 0; o >>= 1) v += __shfl_xor_sync(0xffffffffu, v, o);
    return v;
}
__device__ __forceinline__ float warpMax(float v) {
#pragma unroll
    for (int o = 16; o > 0; o >>= 1) v = fmaxf(v, __shfl_xor_sync(0xffffffffu, v, o));
    return v;
}

// ---------------- generic 64x64x256 fp32 GEMM tile --------------------------
__device__ __forceinline__ void gemm_tile(const float* __restrict__ A, int M,
                                          const float* __restrict__ W,
                                          const float* __restrict__ bias,
                                          float* __restrict__ C, int doRelu,
                                          int srcSkip) {
    __shared__ __align__(16) float Ast[16][64];  // [k][m]
    __shared__ __align__(16) float Ws[16][64];   // [k][n]
    const int tid = threadIdx.x;  // 256 threads
    const int rowBase = blockIdx.y * 64;
    const int colBase = blockIdx.x * 64;
    if (rowBase >= M) return;
    const int tx = tid & 15, ty = tid >> 4;
    float acc[4][4] = {};
    const int aRow = tid >> 2;
    const int aK4 = (tid & 3) * 4;
    const int wK = tid >> 4;
    const int wC4 = (tid & 15) * 4;
    int row = rowBase + aRow;
    int srow = srcSkip ? (row + (row >> 7) + 1) : row;
    for (int k0 = 0; k0 < 256; k0 += 16) {
        float4 av;
        if (row < M)
            av = *(const float4*)(A + (size_t)srow * 256 + k0 + aK4);
        else
            av = make_float4(0.f, 0.f, 0.f, 0.f);
        Ast[aK4 + 0][aRow] = av.x;
        Ast[aK4 + 1][aRow] = av.y;
        Ast[aK4 + 2][aRow] = av.z;
        Ast[aK4 + 3][aRow] = av.w;
        *(float4*)&Ws[wK][wC4] =
            *(const float4*)(W + (size_t)(k0 + wK) * 256 + colBase + wC4);
        __syncthreads();
#pragma unroll
        for (int kk = 0; kk < 16; kk++) {
            float4 a = *(const float4*)&Ast[kk][ty * 4];
            float4 b = *(const float4*)&Ws[kk][tx * 4];
            acc[0][0] += a.x * b.x; acc[0][1] += a.x * b.y; acc[0][2] += a.x * b.z; acc[0][3] += a.x * b.w;
            acc[1][0] += a.y * b.x; acc[1][1] += a.y * b.y; acc[1][2] += a.y * b.z; acc[1][3] += a.y * b.w;
            acc[2][0] += a.z * b.x; acc[2][1] += a.z * b.y; acc[2][2] += a.z * b.z; acc[2][3] += a.z * b.w;
            acc[3][0] += a.w * b.x; acc[3][1] += a.w * b.y; acc[3][2] += a.w * b.z; acc[3][3] += a.w * b.w;
        }
        __syncthreads();
    }
    float4 bv = bias ? *(const float4*)(bias + colBase + tx * 4)
                     : make_float4(0.f, 0.f, 0.f, 0.f);
#pragma unroll
    for (int r = 0; r < 4; r++) {
        int orow = rowBase + ty * 4 + r;
        if (orow < M) {
            float4 o;
            o.x = acc[r][0] + bv.x; o.y = acc[r][1] + bv.y;
            o.z = acc[r][2] + bv.z; o.w = acc[r][3] + bv.w;
            if (doRelu) {
                o.x = fmaxf(o.x, 0.f); o.y = fmaxf(o.y, 0.f);
                o.z = fmaxf(o.z, 0.f); o.w = fmaxf(o.w, 0.f);
            }
            *(float4*)(C + (size_t)orow * 256 + colBase + tx * 4) = o;
        }
    }
}

// ---------------- GEMM phase A: 9 independent GEMMs -------------------------
__global__ __launch_bounds__(256) void phaseA_kernel(
    const float* desc, const float* nv,
    const float* th_w1, const float* th_b1,
    const float* tt_w1, const float* tt_b1,
    const float* ah_w, const float* ah_b,
    const float* at_w, const float* at_b,
    const float* eu_w1, const float* eu_b1,
    const float* q_w, const float* q_b,
    const float* k_w, const float* k_b,
    const float* v_w, const float* v_b) {
    const float *A, *W, *bias;
    float* C;
    int M = 512, relu = 0, skip = 0;
    switch (blockIdx.z) {
        case 0: A = desc; W = th_w1; bias = th_b1; C = g_t1; relu = 1; break;
        case 1: A = desc; W = tt_w1; bias = tt_b1; C = g_t2; relu = 1; break;
        case 2: A = nv;   W = ah_w;  bias = ah_b;  C = g_vh; skip = 1; break;
        case 3: A = nv;   W = at_w;  bias = at_b;  C = g_vt; skip = 1; break;
        case 4: A = desc; W = eu_w1;             bias = eu_b1;  C = g_Pa; break;
        case 5: A = desc; W = eu_w1 + 256 * 256; bias = nullptr; C = g_Pb; break;
        case 6: A = nv;   W = q_w;   bias = q_b;   C = g_q; M = 516; break;
        case 7: A = nv;   W = k_w;   bias = k_b;   C = g_k; M = 516; break;
        default: A = nv;  W = v_w;   bias = v_b;   C = g_v; M = 516; break;
    }
    gemm_tile(A, M, W, bias, C, relu, skip);
}

// ---------------- GEMM phase B: dh, dt --------------------------------------
__global__ __launch_bounds__(256) void phaseB_kernel(
    const float* th_w2, const float* th_b2,
    const float* tt_w2, const float* tt_b2) {
    if (blockIdx.z == 0)
        gemm_tile(g_t1, 512, th_w2, th_b2, g_dh, 0, 0);
    else
        gemm_tile(g_t2, 512, tt_w2, tt_b2, g_dt, 0, 0);
}

// ---------------- combo: qs/ks dots + eu_w2@we fold -------------------------
__global__ __launch_bounds__(256) void combo_kernel(
    const float* __restrict__ ap_w,
    const float* __restrict__ eu_w2,
    const float* __restrict__ eu_b2) {
    int tid = threadIdx.x;  // 256
    int bx = blockIdx.x;
    int w = tid >> 5, lane = tid & 31;
    if (bx < 516) {
        int row = bx;  // b*129+i
        int b = row / 129, iN = row % 129;
        float qv = g_q[(size_t)row * 256 + tid] * ap_w[lane];
        float kv = g_k[(size_t)row * 256 + tid] * ap_w[32 + lane];
        qv = warpSum(qv);
        kv = warpSum(kv);
        if (lane == 0) {
            g_qs[(size_t)(b * 8 + w) * 129 + iN] = qv;
            g_ks[(size_t)(b * 8 + w) * 129 + iN] = kv;
        }
    } else {
        int c = tid;
#pragma unroll
        for (int h = 0; h < 8; h++) {
            float s = 0.f;
#pragma unroll
            for (int t = 0; t < 32; t++)
                s += eu_w2[c * 256 + h * 32 + t] * ap_w[64 + t];
            g_M[c * 8 + h] = s;
        }
        if (tid < 8) {
            float s = 0.f;
#pragma unroll
            for (int t = 0; t < 32; t++) s += eu_b2[tid * 32 + t] * ap_w[64 + t];
            g_biasE[tid] = s;
        }
    }
}

// ---------------- gadj2: G = sigmoid(dh.dt^T norm + tb) * (vh.vt^T) ---------
// 32x32 tiles, D and V products together, row norms accumulated in-flight.
__global__ __launch_bounds__(256) void gadj2_kernel(
    const float* __restrict__ topo) {
    int b = blockIdx.z, it = blockIdx.y, jt = blockIdx.x;
    __shared__ float Ad[16][32], Bd[16][32], Av[16][32], Bv[16][32];
    __shared__ float ssqI[32], ssqJ[32];
    int tid = threadIdx.x;
    if (tid < 32) { ssqI[tid] = 0.f; ssqJ[tid] = 0.f; }
    int grp = tid >> 6;       // 0:dh 1:dt 2:vh 3:vt
    int u = tid & 63;
    int lrow = u & 31;
    int kq = (u >> 5) * 8;    // 0 or 8
    const float* src;
    float (*dst)[32];
    int grow;
    if (grp == 0)      { src = g_dh; grow = b * 128 + it * 32 + lrow; dst = Ad; }
    else if (grp == 1) { src = g_dt; grow = b * 128 + jt * 32 + lrow; dst = Bd; }
    else if (grp == 2) { src = g_vh; grow = b * 128 + it * 32 + lrow; dst = Av; }
    else               { src = g_vt; grow = b * 128 + jt * 32 + lrow; dst = Bv; }
    const float* srow = src + (size_t)grow * 256;
    int tx = tid & 15, ty = tid >> 4;  // 16x16, 2x2 out per thread
    float aD[2][2] = {}, aV[2][2] = {};
    float myssq = 0.f;
    for (int k0 = 0; k0 < 256; k0 += 16) {
        float4 v0 = *(const float4*)(srow + k0 + kq);
        float4 v1 = *(const float4*)(srow + k0 + kq + 4);
        dst[kq + 0][lrow] = v0.x; dst[kq + 1][lrow] = v0.y;
        dst[kq + 2][lrow] = v0.z; dst[kq + 3][lrow] = v0.w;
        dst[kq + 4][lrow] = v1.x; dst[kq + 5][lrow] = v1.y;
        dst[kq + 6][lrow] = v1.z; dst[kq + 7][lrow] = v1.w;
        if (grp < 2)
            myssq += v0.x * v0.x + v0.y * v0.y + v0.z * v0.z + v0.w * v0.w +
                     v1.x * v1.x + v1.y * v1.y + v1.z * v1.z + v1.w * v1.w;
        __syncthreads();
#pragma unroll
        for (int kk = 0; kk < 16; kk++) {
            float a0 = Ad[kk][ty * 2], a1 = Ad[kk][ty * 2 + 1];
            float d0 = Bd[kk][tx * 2], d1 = Bd[kk][tx * 2 + 1];
            aD[0][0] += a0 * d0; aD[0][1] += a0 * d1;
            aD[1][0] += a1 * d0; aD[1][1] += a1 * d1;
            float e0 = Av[kk][ty * 2], e1 = Av[kk][ty * 2 + 1];
            float f0 = Bv[kk][tx * 2], f1 = Bv[kk][tx * 2 + 1];
            aV[0][0] += e0 * f0; aV[0][1] += e0 * f1;
            aV[1][0] += e1 * f0; aV[1][1] += e1 * f1;
        }
        __syncthreads();
    }
    // exactly two adds per row; fl((0+a)+b)==fl((0+b)+a) -> deterministic
    if (grp == 0)      atomicAdd(&ssqI[lrow], myssq);
    else if (grp == 1) atomicAdd(&ssqJ[lrow], myssq);
    __syncthreads();
    float tb = topo[0];
#pragma unroll
    for (int r = 0; r < 2; r++) {
        float invI = rsqrtf(ssqI[ty * 2 + r]);
        int gi = it * 32 + ty * 2 + r;
#pragma unroll
        for (int c = 0; c < 2; c++) {
            int gj = jt * 32 + tx * 2 + c;
            float d = aD[r][c] * invI * rsqrtf(ssqJ[tx * 2 + c]);
            float a = 1.f / (1.f + expf(-(d + tb)));
            float gv = (gi == gj) ? NEGV : a * aV[r][c];
            g_G[((size_t)(b * 128 + gi)) * 128 + gj] = gv;
        }
    }
}

// ---------------- mega: adj row + scores + softmax + ctx per (b,i) ----------
__global__ __launch_bounds__(256) void mega_kernel(
    const float* __restrict__ eu_g, const float* __restrict__ eu_beta,
    const float* __restrict__ ap_b_p, const float* __restrict__ alphap,
    float* __restrict__ attn_out) {
    int i = blockIdx.x;  // 0..128
    int b = blockIdx.y;
    __shared__ __align__(16) float sM[2048];
    __shared__ float sks[1032];
    __shared__ float sqs[8], sbe[8];
    __shared__ __align__(16) float sPa[256];
    __shared__ float sAdj[128];
    __shared__ float sSc[8][132];
    __shared__ float red[8];
    int tid = threadIdx.x, w = tid >> 5, lane = tid & 31;
    int c0 = lane * 8;
    for (int t = tid; t < 2048; t += 256) sM[t] = g_M[t];
    for (int t = tid; t < 1032; t += 256) sks[t] = g_ks[(size_t)b * 1032 + t];
    if (tid < 8) {
        sqs[tid] = g_qs[(size_t)(b * 8 + tid) * 129 + i];
        sbe[tid] = g_biasE[tid];
    }
    if (i >= 1) sPa[tid] = g_Pa[(size_t)(b * 128 + i - 1) * 256 + tid];
    __syncthreads();
    // per-lane register tiles (loop-invariant)
    float Mreg[8][8], greg[8], btreg[8];
#pragma unroll
    for (int u = 0; u < 8; u++) {
        greg[u] = eu_g[c0 + u];
        btreg[u] = eu_beta[c0 + u];
#pragma unroll
        for (int h = 0; h < 8; h++) Mreg[u][h] = sM[(c0 + u) * 8 + h];
    }
    // ---- adj row (i >= 1) ----
    if (i >= 1) {
        size_t r = (size_t)(b * 128 + i - 1) * 128;
        float graw = (tid < 128) ? g_G[r + tid] : NEGV;
        float m = warpMax(graw);
        if (lane == 0) red[w] = m;
        __syncthreads();
        float mx = fmaxf(fmaxf(red[0], red[1]), fmaxf(red[2], red[3]));
        float alpha = fminf(fmaxf(alphap[0], 1e-5f), 1.0f);
        float thr = mx * alpha;
        float e = (tid < 128 && graw >= thr) ? expf(graw - mx) : 0.f;
        float s = warpSum(e);
        __syncthreads();
        if (lane == 0) red[w] = s;
        __syncthreads();
        float Z = red[0] + red[1] + red[2] + red[3] +
                  red[4] + red[5] + red[6] + red[7];
        float invZ = (Z > 0.f) ? 1.f / Z : 0.f;
        if (tid < 128) sAdj[tid] = e * invZ;
        __syncthreads();
    }
    // ---- scores: warp-uniform j ----
    float apb = ap_b_p[0];
    for (int j = w; j < 129; j += 8) {
        float na;
        if (i == 0) na = (j == 0) ? 0.f : 1.f;
        else        na = (j == 0) ? 0.f : sAdj[j - 1];
        float eterm = 0.f;
        if (na != 0.f) {  // warp-uniform
            int rb = b * 128 + j - 1;
            const float4* pb4 = (const float4*)(g_Pb + (size_t)rb * 256 + c0);
            float4 b0 = pb4[0], b1 = pb4[1];
            float vv[8];
            if (i >= 1) {
                vv[0] = sPa[c0 + 0] + b0.x;  vv[1] = sPa[c0 + 1] + b0.y;
                vv[2] = sPa[c0 + 2] + b0.z;  vv[3] = sPa[c0 + 3] + b0.w;
                vv[4] = sPa[c0 + 4] + b1.x;  vv[5] = sPa[c0 + 5] + b1.y;
                vv[6] = sPa[c0 + 6] + b1.z;  vv[7] = sPa[c0 + 7] + b1.w;
            } else {
                const float4* pa4 = (const float4*)(g_Pa + (size_t)rb * 256 + c0);
                float4 a0 = pa4[0], a1 = pa4[1];
                vv[0] = a0.x + b0.x;  vv[1] = a0.y + b0.y;
                vv[2] = a0.z + b0.z;  vv[3] = a0.w + b0.w;
                vv[4] = a1.x + b1.x;  vv[5] = a1.y + b1.y;
                vv[6] = a1.z + b1.z;  vv[7] = a1.w + b1.w;
            }
            float s = 0.f, sq = 0.f;
#pragma unroll
            for (int u = 0; u < 8; u++) { s += vv[u]; sq += vv[u] * vv[u]; }
#pragma unroll
            for (int o = 16; o > 0; o >>= 1) {
                s += __shfl_xor_sync(0xffffffffu, s, o);
                sq += __shfl_xor_sync(0xffffffffu, sq, o);
            }
            float mu = s * (1.f / 256.f);
            float var = sq * (1.f / 256.f) - mu * mu;
            float inv = rsqrtf(var + 1e-5f);
            float acc[8] = {0.f, 0.f, 0.f, 0.f, 0.f, 0.f, 0.f, 0.f};
#pragma unroll
            for (int u = 0; u < 8; u++) {
                float r = fmaxf((vv[u] - mu) * inv * greg[u] + btreg[u], 0.f);
#pragma unroll
                for (int h = 0; h < 8; h++) acc[h] += r * Mreg[u][h];
            }
#pragma unroll
            for (int o = 16; o > 0; o >>= 1) {
#pragma unroll
                for (int h = 0; h < 8; h++)
                    acc[h] += __shfl_xor_sync(0xffffffffu, acc[h], o);
            }
            if (lane < 8) eterm = acc[lane] + sbe[lane];
        }
        if (lane < 8) {
            sSc[lane][j] = sqs[lane] + sks[lane * 129 + j] + apb +
                           ((na == 0.f) ? NEGV : eterm * na);
        }
    }
    __syncthreads();
    // ---- softmax per head (warp w == head) ----
    {
        int h = w;
        float x0 = sSc[h][lane], x1 = sSc[h][lane + 32];
        float x2 = sSc[h][lane + 64], x3 = sSc[h][lane + 96];
        float xt = (lane == 0) ? sSc[h][128] : NEGV;
        float m = fmaxf(fmaxf(x0, x1), fmaxf(fmaxf(x2, x3), xt));
        m = warpMax(m);
        float e0 = expf(x0 - m), e1 = expf(x1 - m);
        float e2 = expf(x2 - m), e3 = expf(x3 - m);
        float et = (lane == 0) ? expf(xt - m) : 0.f;
        float s = e0 + e1 + e2 + e3 + et;
        s = warpSum(s);
        float invZ = 1.f / s;
        sSc[h][lane] = e0 * invZ;
        sSc[h][lane + 32] = e1 * invZ;
        sSc[h][lane + 64] = e2 * invZ;
        sSc[h][lane + 96] = e3 * invZ;
        if (lane == 0) sSc[h][128] = et * invZ;
        if (attn_out) {
            float* ap = attn_out + ((size_t)(b * 8 + h) * 129 + i) * 129;
            ap[lane] = e0 * invZ;
            ap[lane + 32] = e1 * invZ;
            ap[lane + 64] = e2 * invZ;
            ap[lane + 96] = e3 * invZ;
            if (lane == 0) ap[128] = et * invZ;
        }
    }
    __syncthreads();
    // ---- ctx: warp h computes channels h*32+lane ----
    {
        int h = w;
        const float* vbase = g_v + (size_t)b * 129 * 256 + h * 32 + lane;
        float acc = 0.f;
#pragma unroll 4
        for (int j = 0; j < 128; j += 4) {
            acc += sSc[h][j + 0] * vbase[(size_t)(j + 0) * 256];
            acc += sSc[h][j + 1] * vbase[(size_t)(j + 1) * 256];
            acc += sSc[h][j + 2] * vbase[(size_t)(j + 2) * 256];
            acc += sSc[h][j + 3] * vbase[(size_t)(j + 3) * 256];
        }
        acc += sSc[h][128] * vbase[(size_t)128 * 256];
        g_ctx[(size_t)(b * 129 + i) * 256 + h * 32 + lane] = acc;
    }
}

// ---------------- final out GEMM --------------------------------------------
__global__ __launch_bounds__(256) void phaseC_kernel(const float* out_w,
                                                     const float* out_b,
                                                     float* out) {
    gemm_tile(g_ctx, 516, out_w, out_b, out, 0, 0);
}

// ---------------- launch -----------------------------------------------------
extern "C" void kernel_launch(void* const* d_in, const int* in_sizes, int n_in,
                              void* d_out, int out_size) {
    const float* desc   = (const float*)d_in[0];
    const float* nv     = (const float*)d_in[1];
    const float* th_w1  = (const float*)d_in[2];
    const float* th_b1  = (const float*)d_in[3];
    const float* th_w2  = (const float*)d_in[4];
    const float* th_b2  = (const float*)d_in[5];
    const float* tt_w1  = (const float*)d_in[6];
    const float* tt_b1  = (const float*)d_in[7];
    const float* tt_w2  = (const float*)d_in[8];
    const float* tt_b2  = (const float*)d_in[9];
    const float* ah_w   = (const float*)d_in[10];
    const float* ah_b   = (const float*)d_in[11];
    const float* at_w   = (const float*)d_in[12];
    const float* at_b   = (const float*)d_in[13];
    const float* q_w    = (const float*)d_in[14];
    const float* q_b    = (const float*)d_in[15];
    const float* k_w    = (const float*)d_in[16];
    const float* k_b    = (const float*)d_in[17];
    const float* v_w    = (const float*)d_in[18];
    const float* v_b    = (const float*)d_in[19];
    const float* eu_w1  = (const float*)d_in[20];
    const float* eu_b1  = (const float*)d_in[21];
    const float* eu_g   = (const float*)d_in[22];
    const float* eu_beta= (const float*)d_in[23];
    const float* eu_w2  = (const float*)d_in[24];
    const float* eu_b2  = (const float*)d_in[25];
    const float* ap_w   = (const float*)d_in[26];
    const float* ap_b   = (const float*)d_in[27];
    const float* out_w  = (const float*)d_in[28];
    const float* out_b  = (const float*)d_in[29];
    const float* topo   = (const float*)d_in[30];
    const float* alphap = (const float*)d_in[31];

    const int OUT_ELEMS = 4 * 129 * 256;          // 132096
    const int ATTN_ELEMS = 4 * 8 * 129 * 129;     // 532512
    float* out = (float*)d_out;
    float* attn_out = (out_size >= OUT_ELEMS + ATTN_ELEMS) ? (out + OUT_ELEMS)
                                                           : nullptr;

    phaseA_kernel<<<dim3(4, 9, 9), 256>>>(desc, nv, th_w1, th_b1, tt_w1, tt_b1,
                                          ah_w, ah_b, at_w, at_b, eu_w1, eu_b1,
                                          q_w, q_b, k_w, k_b, v_w, v_b);
    phaseB_kernel<<<dim3(4, 8, 2), 256>>>(th_w2, th_b2, tt_w2, tt_b2);
    combo_kernel<<<517, 256>>>(ap_w, eu_w2, eu_b2);
    gadj2_kernel<<<dim3(4, 4, 4), 256>>>(topo);
    mega_kernel<<<dim3(129, 4), 256>>>(eu_g, eu_beta, ap_b, alphap, attn_out);
    phaseC_kernel<<<dim3(4, 9, 1), 256>>>(out_w, out_b, out);
}

// round 5
// speedup vs baseline: 1.5288x; 1.0419x over previous
#include <cuda_runtime.h>
#include <math.h>

// Shapes (fixed): B=4, S=128, D=256, H=8, HD=32, HID=256, NS=129
#define NEGV -1000000000.0f

// ---------------- scratch (device globals) ----------------------------------
__device__ float g_t1[512 * 256];
__device__ float g_t2[512 * 256];
__device__ float g_dh[512 * 256];
__device__ float g_dt[512 * 256];
__device__ float g_vh[512 * 256];
__device__ float g_vt[512 * 256];
__device__ float g_Pa[512 * 256];
__device__ float g_Pb[512 * 256];
__device__ float g_q[516 * 256];
__device__ float g_k[516 * 256];
__device__ float g_v[516 * 256];
__device__ float g_D[4 * 128 * 128];
__device__ float g_V[4 * 128 * 128];
__device__ float g_invDh[512];
__device__ float g_invDt[512];
__device__ float g_qs[4 * 8 * 129];
__device__ float g_ks[4 * 8 * 129];
__device__ float g_ctx[516 * 256];
__device__ float g_M[256 * 8];
__device__ float g_biasE[8];

// ---------------- reduction helpers ----------------------------------------
__device__ __forceinline__ float warpSum(float v) {
#pragma unroll
    for (int o = 16; o > 0; o >>= 1) v += __shfl_xor_sync(0xffffffffu, v, o);
    return v;
}
__device__ __forceinline__ float warpMax(float v) {
#pragma unroll
    for (int o = 16; o > 0; o >>= 1) v = fmaxf(v, __shfl_xor_sync(0xffffffffu, v, o));
    return v;
}

// ---------------- generic 64x64x256 fp32 GEMM tile --------------------------
__device__ __forceinline__ void gemm_tile(const float* __restrict__ A, int M,
                                          const float* __restrict__ W,
                                          const float* __restrict__ bias,
                                          float* __restrict__ C, int doRelu,
                                          int srcSkip) {
    __shared__ __align__(16) float Ast[16][64];  // [k][m]
    __shared__ __align__(16) float Ws[16][64];   // [k][n]
    const int tid = threadIdx.x;  // 256 threads
    const int rowBase = blockIdx.y * 64;
    const int colBase = blockIdx.x * 64;
    if (rowBase >= M) return;
    const int tx = tid & 15, ty = tid >> 4;
    float acc[4][4] = {};
    const int aRow = tid >> 2;
    const int aK4 = (tid & 3) * 4;
    const int wK = tid >> 4;
    const int wC4 = (tid & 15) * 4;
    int row = rowBase + aRow;
    int srow = srcSkip ? (row + (row >> 7) + 1) : row;
    for (int k0 = 0; k0 < 256; k0 += 16) {
        float4 av;
        if (row < M)
            av = *(const float4*)(A + (size_t)srow * 256 + k0 + aK4);
        else
            av = make_float4(0.f, 0.f, 0.f, 0.f);
        Ast[aK4 + 0][aRow] = av.x;
        Ast[aK4 + 1][aRow] = av.y;
        Ast[aK4 + 2][aRow] = av.z;
        Ast[aK4 + 3][aRow] = av.w;
        *(float4*)&Ws[wK][wC4] =
            *(const float4*)(W + (size_t)(k0 + wK) * 256 + colBase + wC4);
        __syncthreads();
#pragma unroll
        for (int kk = 0; kk < 16; kk++) {
            float4 a = *(const float4*)&Ast[kk][ty * 4];
            float4 b = *(const float4*)&Ws[kk][tx * 4];
            acc[0][0] += a.x * b.x; acc[0][1] += a.x * b.y; acc[0][2] += a.x * b.z; acc[0][3] += a.x * b.w;
            acc[1][0] += a.y * b.x; acc[1][1] += a.y * b.y; acc[1][2] += a.y * b.z; acc[1][3] += a.y * b.w;
            acc[2][0] += a.z * b.x; acc[2][1] += a.z * b.y; acc[2][2] += a.z * b.z; acc[2][3] += a.z * b.w;
            acc[3][0] += a.w * b.x; acc[3][1] += a.w * b.y; acc[3][2] += a.w * b.z; acc[3][3] += a.w * b.w;
        }
        __syncthreads();
    }
    float4 bv = bias ? *(const float4*)(bias + colBase + tx * 4)
                     : make_float4(0.f, 0.f, 0.f, 0.f);
#pragma unroll
    for (int r = 0; r < 4; r++) {
        int orow = rowBase + ty * 4 + r;
        if (orow < M) {
            float4 o;
            o.x = acc[r][0] + bv.x; o.y = acc[r][1] + bv.y;
            o.z = acc[r][2] + bv.z; o.w = acc[r][3] + bv.w;
            if (doRelu) {
                o.x = fmaxf(o.x, 0.f); o.y = fmaxf(o.y, 0.f);
                o.z = fmaxf(o.z, 0.f); o.w = fmaxf(o.w, 0.f);
            }
            *(float4*)(C + (size_t)orow * 256 + colBase + tx * 4) = o;
        }
    }
}

// ---------------- GEMM phase A: 9 independent GEMMs -------------------------
__global__ __launch_bounds__(256) void phaseA_kernel(
    const float* desc, const float* nv,
    const float* th_w1, const float* th_b1,
    const float* tt_w1, const float* tt_b1,
    const float* ah_w, const float* ah_b,
    const float* at_w, const float* at_b,
    const float* eu_w1, const float* eu_b1,
    const float* q_w, const float* q_b,
    const float* k_w, const float* k_b,
    const float* v_w, const float* v_b) {
    const float *A, *W, *bias;
    float* C;
    int M = 512, relu = 0, skip = 0;
    switch (blockIdx.z) {
        case 0: A = desc; W = th_w1; bias = th_b1; C = g_t1; relu = 1; break;
        case 1: A = desc; W = tt_w1; bias = tt_b1; C = g_t2; relu = 1; break;
        case 2: A = nv;   W = ah_w;  bias = ah_b;  C = g_vh; skip = 1; break;
        case 3: A = nv;   W = at_w;  bias = at_b;  C = g_vt; skip = 1; break;
        case 4: A = desc; W = eu_w1;             bias = eu_b1;  C = g_Pa; break;
        case 5: A = desc; W = eu_w1 + 256 * 256; bias = nullptr; C = g_Pb; break;
        case 6: A = nv;   W = q_w;   bias = q_b;   C = g_q; M = 516; break;
        case 7: A = nv;   W = k_w;   bias = k_b;   C = g_k; M = 516; break;
        default: A = nv;  W = v_w;   bias = v_b;   C = g_v; M = 516; break;
    }
    gemm_tile(A, M, W, bias, C, relu, skip);
}

// ---------------- GEMM phase B: dh, dt --------------------------------------
__global__ __launch_bounds__(256) void phaseB_kernel(
    const float* th_w2, const float* th_b2,
    const float* tt_w2, const float* tt_b2) {
    if (blockIdx.z == 0)
        gemm_tile(g_t1, 512, th_w2, th_b2, g_dh, 0, 0);
    else
        gemm_tile(g_t2, 512, tt_w2, tt_b2, g_dt, 0, 0);
}

// ---------------- combo: qs/ks dots + M fold + dh/dt row norms --------------
__global__ __launch_bounds__(256) void combo_kernel(
    const float* __restrict__ ap_w,
    const float* __restrict__ eu_w2,
    const float* __restrict__ eu_b2) {
    int tid = threadIdx.x;  // 256
    int bx = blockIdx.x;
    int w = tid >> 5, lane = tid & 31;
    if (bx < 516) {
        int row = bx;  // b*129+i
        int b = row / 129, iN = row % 129;
        float qv = g_q[(size_t)row * 256 + tid] * ap_w[lane];
        float kv = g_k[(size_t)row * 256 + tid] * ap_w[32 + lane];
        qv = warpSum(qv);
        kv = warpSum(kv);
        if (lane == 0) {
            g_qs[(size_t)(b * 8 + w) * 129 + iN] = qv;
            g_ks[(size_t)(b * 8 + w) * 129 + iN] = kv;
        }
    } else if (bx == 516) {
        int c = tid;
#pragma unroll
        for (int h = 0; h < 8; h++) {
            float s = 0.f;
#pragma unroll
            for (int t = 0; t < 32; t++)
                s += eu_w2[c * 256 + h * 32 + t] * ap_w[64 + t];
            g_M[c * 8 + h] = s;
        }
        if (tid < 8) {
            float s = 0.f;
#pragma unroll
            for (int t = 0; t < 32; t++) s += eu_b2[tid * 32 + t] * ap_w[64 + t];
            g_biasE[tid] = s;
        }
    } else {
        // dh/dt row inverse norms: rows 0..1023 (dh 0..511, dt 512..1023)
        int row = (bx - 517) * 8 + w;
        const float* src = (row < 512) ? (g_dh + (size_t)row * 256)
                                       : (g_dt + (size_t)(row - 512) * 256);
        float ss = 0.f;
#pragma unroll
        for (int t = 0; t < 8; t++) {
            float v = src[lane + t * 32];
            ss += v * v;
        }
        ss = warpSum(ss);
        if (lane == 0) {
            float inv = rsqrtf(ss);
            if (row < 512) g_invDh[row] = inv;
            else           g_invDt[row - 512] = inv;
        }
    }
}

// ---------------- products: D = dh.dt^T, V = vh.vt^T (raw, no epilogue) -----
// One 32x32 tile per block, one product per block: grid (4 jt, 4 it, 8 b*p).
__global__ __launch_bounds__(256) void products_kernel() {
    int bp = blockIdx.z;
    int b = bp >> 1, p = bp & 1;
    const float* X = p ? g_vh : g_dh;
    const float* Y = p ? g_vt : g_dt;
    float* C = p ? g_V : g_D;
    __shared__ __align__(16) float As[16][32];
    __shared__ __align__(16) float Bs[16][32];
    int tid = threadIdx.x;
    int it = blockIdx.y, jt = blockIdx.x;
    int grp = tid >> 7;        // 0: X, 1: Y
    int u = tid & 127;
    int lrow = u & 31;
    int kq = (u >> 5) * 4;     // 0,4,8,12
    const float* srow = grp
        ? (Y + (size_t)(b * 128 + jt * 32 + lrow) * 256)
        : (X + (size_t)(b * 128 + it * 32 + lrow) * 256);
    float (*dst)[32] = grp ? Bs : As;
    int tx = tid & 15, ty = tid >> 4;  // 16x16, 2x2 out per thread
    float a00 = 0.f, a01 = 0.f, a10 = 0.f, a11 = 0.f;
    for (int k0 = 0; k0 < 256; k0 += 16) {
        float4 v = *(const float4*)(srow + k0 + kq);
        dst[kq + 0][lrow] = v.x;
        dst[kq + 1][lrow] = v.y;
        dst[kq + 2][lrow] = v.z;
        dst[kq + 3][lrow] = v.w;
        __syncthreads();
#pragma unroll
        for (int kk = 0; kk < 16; kk++) {
            float2 a = *(const float2*)&As[kk][ty * 2];
            float2 bb = *(const float2*)&Bs[kk][tx * 2];
            a00 += a.x * bb.x; a01 += a.x * bb.y;
            a10 += a.y * bb.x; a11 += a.y * bb.y;
        }
        __syncthreads();
    }
    size_t base = ((size_t)(b * 128 + it * 32 + ty * 2)) * 128 + jt * 32 + tx * 2;
    *(float2*)(C + base) = make_float2(a00, a01);
    *(float2*)(C + base + 128) = make_float2(a10, a11);
}

// ---------------- mega: adj row (sigmoid inline) + scores + softmax + ctx ---
__global__ __launch_bounds__(256) void mega_kernel(
    const float* __restrict__ eu_g, const float* __restrict__ eu_beta,
    const float* __restrict__ ap_b_p, const float* __restrict__ topo,
    const float* __restrict__ alphap, float* __restrict__ attn_out) {
    int i = blockIdx.x;  // 0..128
    int b = blockIdx.y;
    __shared__ __align__(16) float sM[2048];
    __shared__ float sks[1032];
    __shared__ float sqs[8], sbe[8];
    __shared__ __align__(16) float sPa[256];
    __shared__ float sAdj[128];
    __shared__ float sSc[8][132];
    __shared__ float red[8];
    int tid = threadIdx.x, w = tid >> 5, lane = tid & 31;
    int c0 = lane * 8;
    for (int t = tid; t < 2048; t += 256) sM[t] = g_M[t];
    for (int t = tid; t < 1032; t += 256) sks[t] = g_ks[(size_t)b * 1032 + t];
    if (tid < 8) {
        sqs[tid] = g_qs[(size_t)(b * 8 + tid) * 129 + i];
        sbe[tid] = g_biasE[tid];
    }
    if (i >= 1) sPa[tid] = g_Pa[(size_t)(b * 128 + i - 1) * 256 + tid];
    __syncthreads();
    // per-lane register tiles (loop-invariant)
    float Mreg[8][8], greg[8], btreg[8];
#pragma unroll
    for (int u = 0; u < 8; u++) {
        greg[u] = eu_g[c0 + u];
        btreg[u] = eu_beta[c0 + u];
#pragma unroll
        for (int h = 0; h < 8; h++) Mreg[u][h] = sM[(c0 + u) * 8 + h];
    }
    // ---- adj row (i >= 1): sigmoid(D_norm + tb) * V, thresholded softmax ----
    if (i >= 1) {
        int r = b * 128 + i - 1;
        float graw = NEGV;
        if (tid < 128) {
            float d = g_D[(size_t)r * 128 + tid] * g_invDh[r] *
                      g_invDt[b * 128 + tid];
            float a = 1.f / (1.f + expf(-(d + topo[0])));
            graw = (tid == i - 1) ? NEGV : a * g_V[(size_t)r * 128 + tid];
        }
        float m = warpMax(graw);
        if (lane == 0) red[w] = m;
        __syncthreads();
        float mx = fmaxf(fmaxf(red[0], red[1]), fmaxf(red[2], red[3]));
        float alpha = fminf(fmaxf(alphap[0], 1e-5f), 1.0f);
        float thr = mx * alpha;
        float e = (tid < 128 && graw >= thr) ? expf(graw - mx) : 0.f;
        float s = warpSum(e);
        __syncthreads();
        if (lane == 0) red[w] = s;
        __syncthreads();
        float Z = red[0] + red[1] + red[2] + red[3] +
                  red[4] + red[5] + red[6] + red[7];
        float invZ = (Z > 0.f) ? 1.f / Z : 0.f;
        if (tid < 128) sAdj[tid] = e * invZ;
        __syncthreads();
    }
    // ---- scores: warp-uniform j ----
    float apb = ap_b_p[0];
    for (int j = w; j < 129; j += 8) {
        float na;
        if (i == 0) na = (j == 0) ? 0.f : 1.f;
        else        na = (j == 0) ? 0.f : sAdj[j - 1];
        float eterm = 0.f;
        if (na != 0.f) {  // warp-uniform
            int rb = b * 128 + j - 1;
            const float4* pb4 = (const float4*)(g_Pb + (size_t)rb * 256 + c0);
            float4 b0 = pb4[0], b1 = pb4[1];
            float vv[8];
            if (i >= 1) {
                vv[0] = sPa[c0 + 0] + b0.x;  vv[1] = sPa[c0 + 1] + b0.y;
                vv[2] = sPa[c0 + 2] + b0.z;  vv[3] = sPa[c0 + 3] + b0.w;
                vv[4] = sPa[c0 + 4] + b1.x;  vv[5] = sPa[c0 + 5] + b1.y;
                vv[6] = sPa[c0 + 6] + b1.z;  vv[7] = sPa[c0 + 7] + b1.w;
            } else {
                const float4* pa4 = (const float4*)(g_Pa + (size_t)rb * 256 + c0);
                float4 a0 = pa4[0], a1 = pa4[1];
                vv[0] = a0.x + b0.x;  vv[1] = a0.y + b0.y;
                vv[2] = a0.z + b0.z;  vv[3] = a0.w + b0.w;
                vv[4] = a1.x + b1.x;  vv[5] = a1.y + b1.y;
                vv[6] = a1.z + b1.z;  vv[7] = a1.w + b1.w;
            }
            float s = 0.f, sq = 0.f;
#pragma unroll
            for (int u = 0; u < 8; u++) { s += vv[u]; sq += vv[u] * vv[u]; }
#pragma unroll
            for (int o = 16; o > 0; o >>= 1) {
                s += __shfl_xor_sync(0xffffffffu, s, o);
                sq += __shfl_xor_sync(0xffffffffu, sq, o);
            }
            float mu = s * (1.f / 256.f);
            float var = sq * (1.f / 256.f) - mu * mu;
            float inv = rsqrtf(var + 1e-5f);
            float acc[8] = {0.f, 0.f, 0.f, 0.f, 0.f, 0.f, 0.f, 0.f};
#pragma unroll
            for (int u = 0; u < 8; u++) {
                float r = fmaxf((vv[u] - mu) * inv * greg[u] + btreg[u], 0.f);
#pragma unroll
                for (int h = 0; h < 8; h++) acc[h] += r * Mreg[u][h];
            }
#pragma unroll
            for (int o = 16; o > 0; o >>= 1) {
#pragma unroll
                for (int h = 0; h < 8; h++)
                    acc[h] += __shfl_xor_sync(0xffffffffu, acc[h], o);
            }
            if (lane < 8) eterm = acc[lane] + sbe[lane];
        }
        if (lane < 8) {
            sSc[lane][j] = sqs[lane] + sks[lane * 129 + j] + apb +
                           ((na == 0.f) ? NEGV : eterm * na);
        }
    }
    __syncthreads();
    // ---- softmax per head (warp w == head) ----
    {
        int h = w;
        float x0 = sSc[h][lane], x1 = sSc[h][lane + 32];
        float x2 = sSc[h][lane + 64], x3 = sSc[h][lane + 96];
        float xt = (lane == 0) ? sSc[h][128] : NEGV;
        float m = fmaxf(fmaxf(x0, x1), fmaxf(fmaxf(x2, x3), xt));
        m = warpMax(m);
        float e0 = expf(x0 - m), e1 = expf(x1 - m);
        float e2 = expf(x2 - m), e3 = expf(x3 - m);
        float et = (lane == 0) ? expf(xt - m) : 0.f;
        float s = e0 + e1 + e2 + e3 + et;
        s = warpSum(s);
        float invZ = 1.f / s;
        sSc[h][lane] = e0 * invZ;
        sSc[h][lane + 32] = e1 * invZ;
        sSc[h][lane + 64] = e2 * invZ;
        sSc[h][lane + 96] = e3 * invZ;
        if (lane == 0) sSc[h][128] = et * invZ;
        if (attn_out) {
            float* ap = attn_out + ((size_t)(b * 8 + h) * 129 + i) * 129;
            ap[lane] = e0 * invZ;
            ap[lane + 32] = e1 * invZ;
            ap[lane + 64] = e2 * invZ;
            ap[lane + 96] = e3 * invZ;
            if (lane == 0) ap[128] = et * invZ;
        }
    }
    __syncthreads();
    // ---- ctx: warp h computes channels h*32+lane ----
    {
        int h = w;
        const float* vbase = g_v + (size_t)b * 129 * 256 + h * 32 + lane;
        float acc = 0.f;
#pragma unroll 4
        for (int j = 0; j < 128; j += 4) {
            acc += sSc[h][j + 0] * vbase[(size_t)(j + 0) * 256];
            acc += sSc[h][j + 1] * vbase[(size_t)(j + 1) * 256];
            acc += sSc[h][j + 2] * vbase[(size_t)(j + 2) * 256];
            acc += sSc[h][j + 3] * vbase[(size_t)(j + 3) * 256];
        }
        acc += sSc[h][128] * vbase[(size_t)128 * 256];
        g_ctx[(size_t)(b * 129 + i) * 256 + h * 32 + lane] = acc;
    }
}

// ---------------- final out GEMM --------------------------------------------
__global__ __launch_bounds__(256) void phaseC_kernel(const float* out_w,
                                                     const float* out_b,
                                                     float* out) {
    gemm_tile(g_ctx, 516, out_w, out_b, out, 0, 0);
}

// ---------------- launch -----------------------------------------------------
extern "C" void kernel_launch(void* const* d_in, const int* in_sizes, int n_in,
                              void* d_out, int out_size) {
    const float* desc   = (const float*)d_in[0];
    const float* nv     = (const float*)d_in[1];
    const float* th_w1  = (const float*)d_in[2];
    const float* th_b1  = (const float*)d_in[3];
    const float* th_w2  = (const float*)d_in[4];
    const float* th_b2  = (const float*)d_in[5];
    const float* tt_w1  = (const float*)d_in[6];
    const float* tt_b1  = (const float*)d_in[7];
    const float* tt_w2  = (const float*)d_in[8];
    const float* tt_b2  = (const float*)d_in[9];
    const float* ah_w   = (const float*)d_in[10];
    const float* ah_b   = (const float*)d_in[11];
    const float* at_w   = (const float*)d_in[12];
    const float* at_b   = (const float*)d_in[13];
    const float* q_w    = (const float*)d_in[14];
    const float* q_b    = (const float*)d_in[15];
    const float* k_w    = (const float*)d_in[16];
    const float* k_b    = (const float*)d_in[17];
    const float* v_w    = (const float*)d_in[18];
    const float* v_b    = (const float*)d_in[19];
    const float* eu_w1  = (const float*)d_in[20];
    const float* eu_b1  = (const float*)d_in[21];
    const float* eu_g   = (const float*)d_in[22];
    const float* eu_beta= (const float*)d_in[23];
    const float* eu_w2  = (const float*)d_in[24];
    const float* eu_b2  = (const float*)d_in[25];
    const float* ap_w   = (const float*)d_in[26];
    const float* ap_b   = (const float*)d_in[27];
    const float* out_w  = (const float*)d_in[28];
    const float* out_b  = (const float*)d_in[29];
    const float* topo   = (const float*)d_in[30];
    const float* alphap = (const float*)d_in[31];

    const int OUT_ELEMS = 4 * 129 * 256;          // 132096
    const int ATTN_ELEMS = 4 * 8 * 129 * 129;     // 532512
    float* out = (float*)d_out;
    float* attn_out = (out_size >= OUT_ELEMS + ATTN_ELEMS) ? (out + OUT_ELEMS)
                                                           : nullptr;

    phaseA_kernel<<<dim3(4, 9, 9), 256>>>(desc, nv, th_w1, th_b1, tt_w1, tt_b1,
                                          ah_w, ah_b, at_w, at_b, eu_w1, eu_b1,
                                          q_w, q_b, k_w, k_b, v_w, v_b);
    phaseB_kernel<<<dim3(4, 8, 2), 256>>>(th_w2, th_b2, tt_w2, tt_b2);
    combo_kernel<<<645, 256>>>(ap_w, eu_w2, eu_b2);
    products_kernel<<<dim3(4, 4, 8), 256>>>();
    mega_kernel<<<dim3(129, 4), 256>>>(eu_g, eu_beta, ap_b, topo, alphap,
                                       attn_out);
    phaseC_kernel<<<dim3(4, 9, 1), 256>>>(out_w, out_b, out);
}

// round 6
// speedup vs baseline: 1.5639x; 1.0230x over previous
#include <cuda_runtime.h>
#include <math.h>

// Shapes (fixed): B=4, S=128, D=256, H=8, HD=32, HID=256, NS=129
#define NEGV -1000000000.0f

// ---------------- scratch (device globals) ----------------------------------
__device__ float g_t1[512 * 256];
__device__ float g_t2[512 * 256];
__device__ float g_dh[512 * 256];
__device__ float g_dt[512 * 256];
__device__ float g_vh[512 * 256];
__device__ float g_vt[512 * 256];
__device__ float g_Pa[512 * 256];
__device__ float g_Pb[512 * 256];
__device__ float g_q[516 * 256];
__device__ float g_k[516 * 256];
__device__ float g_v[516 * 256];
__device__ float g_D[4 * 128 * 128];
__device__ float g_V[4 * 128 * 128];
__device__ float g_invDh[512];
__device__ float g_invDt[512];
__device__ float g_qs[4 * 8 * 129];
__device__ float g_ks[4 * 8 * 129];
__device__ float g_ctx[516 * 256];
__device__ float g_M[256 * 8];
__device__ float g_biasE[8];
__device__ unsigned g_barCount;  // monotonic; never reset (replay-safe)

// ---------------- shared-memory union ---------------------------------------
struct SmemGemm {
    float Ast[16][64];
    float Ws[16][64];
};
struct SmemProd {
    float As[16][32];
    float Bs[16][32];
};
struct SmemMega {
    float sM[2048];
    float sks[1032];
    float sPa[256];
    float sAdj[128];
    float sSc[8][132];
    float red[8];
    float sqs[8];
    float sbe[8];
};
union SmemAll {
    SmemGemm g;
    SmemProd p;
    SmemMega m;
};

// ---------------- helpers ----------------------------------------------------
__device__ __forceinline__ float warpSum(float v) {
#pragma unroll
    for (int o = 16; o > 0; o >>= 1) v += __shfl_xor_sync(0xffffffffu, v, o);
    return v;
}
__device__ __forceinline__ float warpMax(float v) {
#pragma unroll
    for (int o = 16; o > 0; o >>= 1) v = fmaxf(v, __shfl_xor_sync(0xffffffffu, v, o));
    return v;
}

// software grid barrier: monotonic counter, generation = count / gridDim
__device__ __forceinline__ void gridBarrier() {
    __threadfence();
    __syncthreads();
    if (threadIdx.x == 0) {
        unsigned target = gridDim.x;
        unsigned old = atomicAdd(&g_barCount, 1u);
        unsigned need = (old / target + 1u) * target;
        while (atomicAdd(&g_barCount, 0u) < need) {}
        __threadfence();
    }
    __syncthreads();
}

// ---------------- 64x64x256 fp32 GEMM tile ----------------------------------
__device__ void gemm_tile_f(SmemGemm& S, int rowTile, int colTile,
                            const float* __restrict__ A, int M,
                            const float* __restrict__ W,
                            const float* __restrict__ bias,
                            float* __restrict__ C, int doRelu, int srcSkip) {
    const int tid = threadIdx.x;
    const int rowBase = rowTile * 64;
    const int colBase = colTile * 64;
    if (rowBase >= M) return;  // block-uniform
    const int tx = tid & 15, ty = tid >> 4;
    float acc[4][4] = {};
    const int aRow = tid >> 2;
    const int aK4 = (tid & 3) * 4;
    const int wK = tid >> 4;
    const int wC4 = (tid & 15) * 4;
    int row = rowBase + aRow;
    int srow = srcSkip ? (row + (row >> 7) + 1) : row;
    for (int k0 = 0; k0 < 256; k0 += 16) {
        float4 av;
        if (row < M)
            av = *(const float4*)(A + (size_t)srow * 256 + k0 + aK4);
        else
            av = make_float4(0.f, 0.f, 0.f, 0.f);
        S.Ast[aK4 + 0][aRow] = av.x;
        S.Ast[aK4 + 1][aRow] = av.y;
        S.Ast[aK4 + 2][aRow] = av.z;
        S.Ast[aK4 + 3][aRow] = av.w;
        *(float4*)&S.Ws[wK][wC4] =
            *(const float4*)(W + (size_t)(k0 + wK) * 256 + colBase + wC4);
        __syncthreads();
#pragma unroll
        for (int kk = 0; kk < 16; kk++) {
            float4 a = *(const float4*)&S.Ast[kk][ty * 4];
            float4 b = *(const float4*)&S.Ws[kk][tx * 4];
            acc[0][0] += a.x * b.x; acc[0][1] += a.x * b.y; acc[0][2] += a.x * b.z; acc[0][3] += a.x * b.w;
            acc[1][0] += a.y * b.x; acc[1][1] += a.y * b.y; acc[1][2] += a.y * b.z; acc[1][3] += a.y * b.w;
            acc[2][0] += a.z * b.x; acc[2][1] += a.z * b.y; acc[2][2] += a.z * b.z; acc[2][3] += a.z * b.w;
            acc[3][0] += a.w * b.x; acc[3][1] += a.w * b.y; acc[3][2] += a.w * b.z; acc[3][3] += a.w * b.w;
        }
        __syncthreads();
    }
    float4 bv = bias ? *(const float4*)(bias + colBase + tx * 4)
                     : make_float4(0.f, 0.f, 0.f, 0.f);
#pragma unroll
    for (int r = 0; r < 4; r++) {
        int orow = rowBase + ty * 4 + r;
        if (orow < M) {
            float4 o;
            o.x = acc[r][0] + bv.x; o.y = acc[r][1] + bv.y;
            o.z = acc[r][2] + bv.z; o.w = acc[r][3] + bv.w;
            if (doRelu) {
                o.x = fmaxf(o.x, 0.f); o.y = fmaxf(o.y, 0.f);
                o.z = fmaxf(o.z, 0.f); o.w = fmaxf(o.w, 0.f);
            }
            *(float4*)(C + (size_t)orow * 256 + colBase + tx * 4) = o;
        }
    }
}

// ---------------- products 32x32 tile (D or V) -------------------------------
__device__ void products_tile(SmemProd& S, int pt) {
    int jt = pt & 3, it = (pt >> 2) & 3, bp = pt >> 4;
    int b = bp >> 1, p = bp & 1;
    const float* X = p ? g_vh : g_dh;
    const float* Y = p ? g_vt : g_dt;
    float* C = p ? g_V : g_D;
    int tid = threadIdx.x;
    int grp = tid >> 7;
    int u = tid & 127;
    int lrow = u & 31;
    int kq = (u >> 5) * 4;
    const float* srow = grp
        ? (Y + (size_t)(b * 128 + jt * 32 + lrow) * 256)
        : (X + (size_t)(b * 128 + it * 32 + lrow) * 256);
    float (*dst)[32] = grp ? S.Bs : S.As;
    int tx = tid & 15, ty = tid >> 4;
    float a00 = 0.f, a01 = 0.f, a10 = 0.f, a11 = 0.f;
    for (int k0 = 0; k0 < 256; k0 += 16) {
        float4 v = *(const float4*)(srow + k0 + kq);
        dst[kq + 0][lrow] = v.x;
        dst[kq + 1][lrow] = v.y;
        dst[kq + 2][lrow] = v.z;
        dst[kq + 3][lrow] = v.w;
        __syncthreads();
#pragma unroll
        for (int kk = 0; kk < 16; kk++) {
            float2 a = *(const float2*)&S.As[kk][ty * 2];
            float2 bb = *(const float2*)&S.Bs[kk][tx * 2];
            a00 += a.x * bb.x; a01 += a.x * bb.y;
            a10 += a.y * bb.x; a11 += a.y * bb.y;
        }
        __syncthreads();
    }
    size_t base = ((size_t)(b * 128 + it * 32 + ty * 2)) * 128 + jt * 32 + tx * 2;
    *(float2*)(C + base) = make_float2(a00, a01);
    *(float2*)(C + base + 128) = make_float2(a10, a11);
}

// ---------------- combo tile -------------------------------------------------
__device__ void combo_tile(int bx, const float* __restrict__ ap_w,
                           const float* __restrict__ eu_w2,
                           const float* __restrict__ eu_b2) {
    int tid = threadIdx.x;
    int w = tid >> 5, lane = tid & 31;
    if (bx < 516) {
        int row = bx;
        int b = row / 129, iN = row % 129;
        float qv = g_q[(size_t)row * 256 + tid] * ap_w[lane];
        float kv = g_k[(size_t)row * 256 + tid] * ap_w[32 + lane];
        qv = warpSum(qv);
        kv = warpSum(kv);
        if (lane == 0) {
            g_qs[(size_t)(b * 8 + w) * 129 + iN] = qv;
            g_ks[(size_t)(b * 8 + w) * 129 + iN] = kv;
        }
    } else if (bx == 516) {
        int c = tid;
#pragma unroll
        for (int h = 0; h < 8; h++) {
            float s = 0.f;
#pragma unroll
            for (int t = 0; t < 32; t++)
                s += eu_w2[c * 256 + h * 32 + t] * ap_w[64 + t];
            g_M[c * 8 + h] = s;
        }
        if (tid < 8) {
            float s = 0.f;
#pragma unroll
            for (int t = 0; t < 32; t++) s += eu_b2[tid * 32 + t] * ap_w[64 + t];
            g_biasE[tid] = s;
        }
    } else {
        int row = (bx - 517) * 8 + w;
        const float* src = (row < 512) ? (g_dh + (size_t)row * 256)
                                       : (g_dt + (size_t)(row - 512) * 256);
        float ss = 0.f;
#pragma unroll
        for (int t = 0; t < 8; t++) {
            float v = src[lane + t * 32];
            ss += v * v;
        }
        ss = warpSum(ss);
        if (lane == 0) {
            float inv = rsqrtf(ss);
            if (row < 512) g_invDh[row] = inv;
            else           g_invDt[row - 512] = inv;
        }
    }
}

// ---------------- mega tile: adj + scores + softmax + ctx for (b,i) ----------
__device__ void mega_tile(SmemMega& S, int i, int b,
                          const float* __restrict__ eu_g,
                          const float* __restrict__ eu_beta,
                          const float* __restrict__ ap_b_p,
                          const float* __restrict__ topo,
                          const float* __restrict__ alphap,
                          float* __restrict__ attn_out) {
    int tid = threadIdx.x, w = tid >> 5, lane = tid & 31;
    int c0 = lane * 8;
    for (int t = tid; t < 2048; t += 256) S.sM[t] = g_M[t];
    for (int t = tid; t < 1032; t += 256) S.sks[t] = g_ks[(size_t)b * 1032 + t];
    if (tid < 8) {
        S.sqs[tid] = g_qs[(size_t)(b * 8 + tid) * 129 + i];
        S.sbe[tid] = g_biasE[tid];
    }
    if (i >= 1) S.sPa[tid] = g_Pa[(size_t)(b * 128 + i - 1) * 256 + tid];
    __syncthreads();
    float Mreg[8][8], greg[8], btreg[8];
#pragma unroll
    for (int u = 0; u < 8; u++) {
        greg[u] = eu_g[c0 + u];
        btreg[u] = eu_beta[c0 + u];
#pragma unroll
        for (int h = 0; h < 8; h++) Mreg[u][h] = S.sM[(c0 + u) * 8 + h];
    }
    // ---- adj row (i >= 1) ----
    if (i >= 1) {
        int r = b * 128 + i - 1;
        float graw = NEGV;
        if (tid < 128) {
            float d = g_D[(size_t)r * 128 + tid] * g_invDh[r] *
                      g_invDt[b * 128 + tid];
            float a = 1.f / (1.f + expf(-(d + topo[0])));
            graw = (tid == i - 1) ? NEGV : a * g_V[(size_t)r * 128 + tid];
        }
        float m = warpMax(graw);
        if (lane == 0) S.red[w] = m;
        __syncthreads();
        float mx = fmaxf(fmaxf(S.red[0], S.red[1]), fmaxf(S.red[2], S.red[3]));
        float alpha = fminf(fmaxf(alphap[0], 1e-5f), 1.0f);
        float thr = mx * alpha;
        float e = (tid < 128 && graw >= thr) ? expf(graw - mx) : 0.f;
        float s = warpSum(e);
        __syncthreads();
        if (lane == 0) S.red[w] = s;
        __syncthreads();
        float Z = S.red[0] + S.red[1] + S.red[2] + S.red[3] +
                  S.red[4] + S.red[5] + S.red[6] + S.red[7];
        float invZ = (Z > 0.f) ? 1.f / Z : 0.f;
        if (tid < 128) S.sAdj[tid] = e * invZ;
        __syncthreads();
    }
    // ---- scores ----
    float apb = ap_b_p[0];
    for (int j = w; j < 129; j += 8) {
        float na;
        if (i == 0) na = (j == 0) ? 0.f : 1.f;
        else        na = (j == 0) ? 0.f : S.sAdj[j - 1];
        float eterm = 0.f;
        if (na != 0.f) {
            int rb = b * 128 + j - 1;
            const float4* pb4 = (const float4*)(g_Pb + (size_t)rb * 256 + c0);
            float4 b0 = pb4[0], b1 = pb4[1];
            float vv[8];
            if (i >= 1) {
                vv[0] = S.sPa[c0 + 0] + b0.x;  vv[1] = S.sPa[c0 + 1] + b0.y;
                vv[2] = S.sPa[c0 + 2] + b0.z;  vv[3] = S.sPa[c0 + 3] + b0.w;
                vv[4] = S.sPa[c0 + 4] + b1.x;  vv[5] = S.sPa[c0 + 5] + b1.y;
                vv[6] = S.sPa[c0 + 6] + b1.z;  vv[7] = S.sPa[c0 + 7] + b1.w;
            } else {
                const float4* pa4 = (const float4*)(g_Pa + (size_t)rb * 256 + c0);
                float4 a0 = pa4[0], a1 = pa4[1];
                vv[0] = a0.x + b0.x;  vv[1] = a0.y + b0.y;
                vv[2] = a0.z + b0.z;  vv[3] = a0.w + b0.w;
                vv[4] = a1.x + b1.x;  vv[5] = a1.y + b1.y;
                vv[6] = a1.z + b1.z;  vv[7] = a1.w + b1.w;
            }
            float s = 0.f, sq = 0.f;
#pragma unroll
            for (int u = 0; u < 8; u++) { s += vv[u]; sq += vv[u] * vv[u]; }
#pragma unroll
            for (int o = 16; o > 0; o >>= 1) {
                s += __shfl_xor_sync(0xffffffffu, s, o);
                sq += __shfl_xor_sync(0xffffffffu, sq, o);
            }
            float mu = s * (1.f / 256.f);
            float var = sq * (1.f / 256.f) - mu * mu;
            float inv = rsqrtf(var + 1e-5f);
            float acc[8] = {0.f, 0.f, 0.f, 0.f, 0.f, 0.f, 0.f, 0.f};
#pragma unroll
            for (int u = 0; u < 8; u++) {
                float r = fmaxf((vv[u] - mu) * inv * greg[u] + btreg[u], 0.f);
#pragma unroll
                for (int h = 0; h < 8; h++) acc[h] += r * Mreg[u][h];
            }
#pragma unroll
            for (int o = 16; o > 0; o >>= 1) {
#pragma unroll
                for (int h = 0; h < 8; h++)
                    acc[h] += __shfl_xor_sync(0xffffffffu, acc[h], o);
            }
            if (lane < 8) eterm = acc[lane] + S.sbe[lane];
        }
        if (lane < 8) {
            S.sSc[lane][j] = S.sqs[lane] + S.sks[lane * 129 + j] + apb +
                             ((na == 0.f) ? NEGV : eterm * na);
        }
    }
    __syncthreads();
    // ---- softmax per head ----
    {
        int h = w;
        float x0 = S.sSc[h][lane], x1 = S.sSc[h][lane + 32];
        float x2 = S.sSc[h][lane + 64], x3 = S.sSc[h][lane + 96];
        float xt = (lane == 0) ? S.sSc[h][128] : NEGV;
        float m = fmaxf(fmaxf(x0, x1), fmaxf(fmaxf(x2, x3), xt));
        m = warpMax(m);
        float e0 = expf(x0 - m), e1 = expf(x1 - m);
        float e2 = expf(x2 - m), e3 = expf(x3 - m);
        float et = (lane == 0) ? expf(xt - m) : 0.f;
        float s = e0 + e1 + e2 + e3 + et;
        s = warpSum(s);
        float invZ = 1.f / s;
        S.sSc[h][lane] = e0 * invZ;
        S.sSc[h][lane + 32] = e1 * invZ;
        S.sSc[h][lane + 64] = e2 * invZ;
        S.sSc[h][lane + 96] = e3 * invZ;
        if (lane == 0) S.sSc[h][128] = et * invZ;
        if (attn_out) {
            float* ap = attn_out + ((size_t)(b * 8 + h) * 129 + i) * 129;
            ap[lane] = e0 * invZ;
            ap[lane + 32] = e1 * invZ;
            ap[lane + 64] = e2 * invZ;
            ap[lane + 96] = e3 * invZ;
            if (lane == 0) ap[128] = et * invZ;
        }
    }
    __syncthreads();
    // ---- ctx ----
    {
        int h = w;
        const float* vbase = g_v + (size_t)b * 129 * 256 + h * 32 + lane;
        float acc = 0.f;
#pragma unroll 4
        for (int j = 0; j < 128; j += 4) {
            acc += S.sSc[h][j + 0] * vbase[(size_t)(j + 0) * 256];
            acc += S.sSc[h][j + 1] * vbase[(size_t)(j + 1) * 256];
            acc += S.sSc[h][j + 2] * vbase[(size_t)(j + 2) * 256];
            acc += S.sSc[h][j + 3] * vbase[(size_t)(j + 3) * 256];
        }
        acc += S.sSc[h][128] * vbase[(size_t)128 * 256];
        g_ctx[(size_t)(b * 129 + i) * 256 + h * 32 + lane] = acc;
    }
    __syncthreads();  // protect shared before next tile reuses it
}

// ---------------- the single fused kernel ------------------------------------
extern "C" __global__ void __launch_bounds__(256, 2) fused_kernel(
    const float* desc, const float* nv,
    const float* th_w1, const float* th_b1,
    const float* th_w2, const float* th_b2,
    const float* tt_w1, const float* tt_b1,
    const float* tt_w2, const float* tt_b2,
    const float* ah_w, const float* ah_b,
    const float* at_w, const float* at_b,
    const float* q_w, const float* q_b,
    const float* k_w, const float* k_b,
    const float* v_w, const float* v_b,
    const float* eu_w1, const float* eu_b1,
    const float* eu_g, const float* eu_beta,
    const float* eu_w2, const float* eu_b2,
    const float* ap_w, const float* ap_b,
    const float* out_w, const float* out_b,
    const float* topo, const float* alphap,
    float* out, float* attn_out) {
    __shared__ SmemAll sm;

    // ---- Phase A: 9 GEMMs, 324 tiles ----
    for (int t = blockIdx.x; t < 324; t += gridDim.x) {
        int col = t & 3, row = (t >> 2) % 9, which = t / 36;
        const float *A, *W, *bias;
        float* C;
        int M = 512, relu = 0, skip = 0;
        switch (which) {
            case 0: A = desc; W = th_w1; bias = th_b1; C = g_t1; relu = 1; break;
            case 1: A = desc; W = tt_w1; bias = tt_b1; C = g_t2; relu = 1; break;
            case 2: A = nv;   W = ah_w;  bias = ah_b;  C = g_vh; skip = 1; break;
            case 3: A = nv;   W = at_w;  bias = at_b;  C = g_vt; skip = 1; break;
            case 4: A = desc; W = eu_w1;             bias = eu_b1;  C = g_Pa; break;
            case 5: A = desc; W = eu_w1 + 256 * 256; bias = nullptr; C = g_Pb; break;
            case 6: A = nv;   W = q_w;   bias = q_b;   C = g_q; M = 516; break;
            case 7: A = nv;   W = k_w;   bias = k_b;   C = g_k; M = 516; break;
            default: A = nv;  W = v_w;   bias = v_b;   C = g_v; M = 516; break;
        }
        gemm_tile_f(sm.g, row, col, A, M, W, bias, C, relu, skip);
    }
    gridBarrier();

    // ---- Phase B: dh, dt (64 tiles) ----
    for (int t = blockIdx.x; t < 64; t += gridDim.x) {
        int col = t & 3, row = (t >> 2) & 7, which = t >> 5;
        if (which == 0)
            gemm_tile_f(sm.g, row, col, g_t1, 512, th_w2, th_b2, g_dh, 0, 0);
        else
            gemm_tile_f(sm.g, row, col, g_t2, 512, tt_w2, tt_b2, g_dt, 0, 0);
    }
    gridBarrier();

    // ---- Phase CP: combo (645) + products (128) = 773 tiles ----
    for (int t = blockIdx.x; t < 773; t += gridDim.x) {
        if (t < 645) combo_tile(t, ap_w, eu_w2, eu_b2);
        else         products_tile(sm.p, t - 645);
        __syncthreads();
    }
    gridBarrier();

    // ---- Phase mega: 516 tiles ----
    for (int t = blockIdx.x; t < 516; t += gridDim.x)
        mega_tile(sm.m, t % 129, t / 129, eu_g, eu_beta, ap_b, topo, alphap,
                  attn_out);
    gridBarrier();

    // ---- Phase C: out GEMM (36 tiles) ----
    for (int t = blockIdx.x; t < 36; t += gridDim.x)
        gemm_tile_f(sm.g, t >> 2, t & 3, g_ctx, 516, out_w, out_b, out, 0, 0);
}

// ---------------- launch -----------------------------------------------------
extern "C" void kernel_launch(void* const* d_in, const int* in_sizes, int n_in,
                              void* d_out, int out_size) {
    const float* desc   = (const float*)d_in[0];
    const float* nv     = (const float*)d_in[1];
    const float* th_w1  = (const float*)d_in[2];
    const float* th_b1  = (const float*)d_in[3];
    const float* th_w2  = (const float*)d_in[4];
    const float* th_b2  = (const float*)d_in[5];
    const float* tt_w1  = (const float*)d_in[6];
    const float* tt_b1  = (const float*)d_in[7];
    const float* tt_w2  = (const float*)d_in[8];
    const float* tt_b2  = (const float*)d_in[9];
    const float* ah_w   = (const float*)d_in[10];
    const float* ah_b   = (const float*)d_in[11];
    const float* at_w   = (const float*)d_in[12];
    const float* at_b   = (const float*)d_in[13];
    const float* q_w    = (const float*)d_in[14];
    const float* q_b    = (const float*)d_in[15];
    const float* k_w    = (const float*)d_in[16];
    const float* k_b    = (const float*)d_in[17];
    const float* v_w    = (const float*)d_in[18];
    const float* v_b    = (const float*)d_in[19];
    const float* eu_w1  = (const float*)d_in[20];
    const float* eu_b1  = (const float*)d_in[21];
    const float* eu_g   = (const float*)d_in[22];
    const float* eu_beta= (const float*)d_in[23];
    const float* eu_w2  = (const float*)d_in[24];
    const float* eu_b2  = (const float*)d_in[25];
    const float* ap_w   = (const float*)d_in[26];
    const float* ap_b   = (const float*)d_in[27];
    const float* out_w  = (const float*)d_in[28];
    const float* out_b  = (const float*)d_in[29];
    const float* topo   = (const float*)d_in[30];
    const float* alphap = (const float*)d_in[31];

    const int OUT_ELEMS = 4 * 129 * 256;          // 132096
    const int ATTN_ELEMS = 4 * 8 * 129 * 129;     // 532512
    float* out = (float*)d_out;
    float* attn_out = (out_size >= OUT_ELEMS + ATTN_ELEMS) ? (out + OUT_ELEMS)
                                                           : nullptr;

    int dev = 0;
    cudaGetDevice(&dev);
    int sms = 0;
    cudaDeviceGetAttribute(&sms, cudaDevAttrMultiProcessorCount, dev);
    int occ = 0;
    cudaOccupancyMaxActiveBlocksPerMultiprocessor(&occ, fused_kernel, 256, 0);
    if (occ < 1) occ = 1;
    if (occ > 4) occ = 4;
    int grid = sms * occ;  // co-resident by construction -> barrier is safe

    fused_kernel<<<grid, 256>>>(
        desc, nv, th_w1, th_b1, th_w2, th_b2, tt_w1, tt_b1, tt_w2, tt_b2,
        ah_w, ah_b, at_w, at_b, q_w, q_b, k_w, k_b, v_w, v_b,
        eu_w1, eu_b1, eu_g, eu_beta, eu_w2, eu_b2, ap_w, ap_b,
        out_w, out_b, topo, alphap, out, attn_out);
}